// round 1
// baseline (speedup 1.0000x reference)
#include <cuda_runtime.h>
#include <cstdint>
#include <cstddef>

// ---------------- problem constants ----------------
#define Hh_ 384
#define Ww_ 384
#define C_ 200
#define N_ 147456           // Hh_*Ww_
#define E_ 1179648
#define HIDE_ 128
#define OUT_ 64
#define NCLS_ 16
#define EPS_ 1e-5f
#define SLOPE_ 0.01f

// ---------------- scratch (device globals; no allocation allowed) ----------------
__device__ float g_P[(size_t)N_ * 128];     // layer in/out (clean, gcn out)
__device__ float g_Q[(size_t)N_ * 128];     // normalized / staging
__device__ float g_Hm[(size_t)N_ * 128];    // h = x @ W
__device__ float g_cnn[(size_t)N_ * 64];
__device__ float g_cnnres[(size_t)N_ * 64];
__device__ float g_deg[N_];
__device__ float g_dinv[N_];
__device__ float g_sum[256];
__device__ float g_sq[256];
__device__ float g_wf[C_ * 128];            // folded weights (max 200x128)
__device__ float g_bf[128];                 // folded bias

// ---------------- small utility kernels ----------------
__global__ void k_zero_stats() {
    int i = threadIdx.x;
    if (i < 256) { g_sum[i] = 0.f; g_sq[i] = 0.f; }
}

// column stats: blockDim == C, 128 blocks, each covers N_/128 rows (coalesced)
template <int C>
__global__ void k_colstats(const float* __restrict__ X) {
    const int c = threadIdx.x;
    const int rpb = N_ / 128;
    const int r0 = blockIdx.x * rpb;
    float s = 0.f, q = 0.f;
    for (int r = r0; r < r0 + rpb; ++r) {
        float v = X[(size_t)r * C + c];
        s += v; q += v * v;
    }
    atomicAdd(&g_sum[c], s);
    atomicAdd(&g_sq[c], q);
}

// Wf[c][m] = scale_c * W[c][m]
template <int K, int M>
__global__ void k_foldw(const float* __restrict__ W, const float* __restrict__ bng) {
    int i = blockIdx.x * blockDim.x + threadIdx.x;
    if (i >= K * M) return;
    int c = i / M;
    float mean = g_sum[c] * (1.0f / N_);
    float var  = g_sq[c] * (1.0f / N_) - mean * mean;
    float scale = bng[c] * rsqrtf(var + EPS_);
    g_wf[i] = scale * W[i];
}

// bf[m] = bias[m] + sum_c shift_c * W[c][m]
template <int K, int M>
__global__ void k_foldb(const float* __restrict__ W, const float* __restrict__ bng,
                        const float* __restrict__ bnb, const float* __restrict__ bias) {
    int m = threadIdx.x;  // blockDim == M
    float acc = bias ? bias[m] : 0.0f;
    for (int c = 0; c < K; ++c) {
        float mean = g_sum[c] * (1.0f / N_);
        float var  = g_sq[c] * (1.0f / N_) - mean * mean;
        float scale = bng[c] * rsqrtf(var + EPS_);
        float shift = bnb[c] - mean * scale;
        acc += shift * W[c * M + m];
    }
    g_bf[m] = acc;
}

// ---------------- GEMM: Y[N,M] = act(X[N,K] @ g_wf + g_bf) ----------------
// 256 threads, BM rows per block, thread tile 8 rows x 8 cols, f32x2 FMA.
template <int K, int M, int BM, int TCOLS, bool LEAKY>
__global__ __launch_bounds__(256, 1)
void k_gemm(const float* __restrict__ X, float* __restrict__ Y) {
    extern __shared__ float sm[];
    float* Ws = sm;                 // K*M
    float* Xs = sm + K * M;         // BM*(K+1), padded to kill bank conflicts
    const int tid = threadIdx.x;
    const size_t row0 = (size_t)blockIdx.x * BM;

    for (int i = tid; i < K * M; i += 256) Ws[i] = g_wf[i];
    for (int i = tid; i < BM * K; i += 256) {
        int r = i / K, k = i - r * K;
        Xs[r * (K + 1) + k] = X[(row0 + r) * K + k];
    }
    __syncthreads();

    const int tc = tid % TCOLS, tr = tid / TCOLS;
    const int c0 = tc * 8, r0 = tr * 8;

    unsigned long long acc[8][4];
    unsigned long long binit[4];
#pragma unroll
    for (int j = 0; j < 4; ++j) {
        unsigned lo = __float_as_uint(g_bf[c0 + 2 * j]);
        unsigned hi = __float_as_uint(g_bf[c0 + 2 * j + 1]);
        asm("mov.b64 %0, {%1,%2};" : "=l"(binit[j]) : "r"(lo), "r"(hi));
    }
#pragma unroll
    for (int i = 0; i < 8; ++i)
#pragma unroll
        for (int j = 0; j < 4; ++j) acc[i][j] = binit[j];

#pragma unroll 4
    for (int k = 0; k < K; ++k) {
        const ulonglong2 wA = *(const ulonglong2*)&Ws[k * M + c0];
        const ulonglong2 wB = *(const ulonglong2*)&Ws[k * M + c0 + 4];
#pragma unroll
        for (int i = 0; i < 8; ++i) {
            unsigned xv = __float_as_uint(Xs[(r0 + i) * (K + 1) + k]);
            unsigned long long xp;
            asm("mov.b64 %0, {%1,%1};" : "=l"(xp) : "r"(xv));
            asm("fma.rn.f32x2 %0, %1, %2, %0;" : "+l"(acc[i][0]) : "l"(xp), "l"(wA.x));
            asm("fma.rn.f32x2 %0, %1, %2, %0;" : "+l"(acc[i][1]) : "l"(xp), "l"(wA.y));
            asm("fma.rn.f32x2 %0, %1, %2, %0;" : "+l"(acc[i][2]) : "l"(xp), "l"(wB.x));
            asm("fma.rn.f32x2 %0, %1, %2, %0;" : "+l"(acc[i][3]) : "l"(xp), "l"(wB.y));
        }
    }

#pragma unroll
    for (int i = 0; i < 8; ++i) {
        float outv[8];
#pragma unroll
        for (int j = 0; j < 4; ++j) {
            unsigned lo, hi;
            asm("mov.b64 {%0,%1}, %2;" : "=r"(lo), "=r"(hi) : "l"(acc[i][j]));
            outv[2 * j]     = __uint_as_float(lo);
            outv[2 * j + 1] = __uint_as_float(hi);
        }
        if (LEAKY) {
#pragma unroll
            for (int j = 0; j < 8; ++j) outv[j] = outv[j] > 0.f ? outv[j] : SLOPE_ * outv[j];
        }
        float* yp = &Y[(row0 + r0 + i) * M + c0];
        *(float4*)(yp)     = *(float4*)&outv[0];
        *(float4*)(yp + 4) = *(float4*)&outv[4];
    }
}

// ---------------- rownorm (F.normalize) : warp per 128-float row ----------------
__global__ void k_rownorm(const float* __restrict__ X, float* __restrict__ Y) {
    int w = (blockIdx.x * blockDim.x + threadIdx.x) >> 5;
    if (w >= N_) return;
    int lane = threadIdx.x & 31;
    float4 v = *(const float4*)&X[(size_t)w * 128 + lane * 4];
    float ss = v.x * v.x + v.y * v.y + v.z * v.z + v.w * v.w;
#pragma unroll
    for (int o = 16; o > 0; o >>= 1) ss += __shfl_xor_sync(0xffffffffu, ss, o);
    float inv = 1.0f / fmaxf(sqrtf(ss), 1e-12f);
    v.x *= inv; v.y *= inv; v.z *= inv; v.w *= inv;
    *(float4*)&Y[(size_t)w * 128 + lane * 4] = v;
}

// ---------------- degree / dinv ----------------
__global__ void k_deg_init() {
    int i = blockIdx.x * blockDim.x + threadIdx.x;
    if (i < N_) g_deg[i] = 1.0f;   // self loop
}
__global__ void k_deg_count(const int* __restrict__ dst) {
    int e = blockIdx.x * blockDim.x + threadIdx.x;
    if (e < E_) atomicAdd(&g_deg[dst[e]], 1.0f);
}
__global__ void k_deg_fin() {
    int i = blockIdx.x * blockDim.x + threadIdx.x;
    if (i < N_) g_dinv[i] = rsqrtf(g_deg[i]);
}

// ---------------- GCN aggregation ----------------
// out[i][c] = g_b[c] + h[i][c]*dinv[i]^2   (self loop + bias init)
template <int D>
__global__ void k_gcn_init(const float* __restrict__ Hm, const float* __restrict__ gb,
                           float* __restrict__ out) {
    size_t idx = (size_t)blockIdx.x * blockDim.x + threadIdx.x;
    if (idx >= (size_t)N_ * D) return;
    int i = (int)(idx / D), c = (int)(idx % D);
    float di = g_dinv[i];
    out[idx] = gb[c] + Hm[idx] * di * di;
}

// warp per edge: out[d] += h[s] * dinv[s]*dinv[d]  via vector reductions
template <int D>
__global__ void k_gcn_scatter(const float* __restrict__ Hm, const int* __restrict__ src,
                              const int* __restrict__ dst, float* __restrict__ out) {
    int e = (int)(((size_t)blockIdx.x * blockDim.x + threadIdx.x) >> 5);
    if (e >= E_) return;
    int lane = threadIdx.x & 31;
    int s = __ldg(&src[e]);
    int d = __ldg(&dst[e]);
    float nrm = g_dinv[s] * g_dinv[d];
    if (D == 128) {
        float4 v = *(const float4*)&Hm[(size_t)s * 128 + lane * 4];
        v.x *= nrm; v.y *= nrm; v.z *= nrm; v.w *= nrm;
        float* p = &out[(size_t)d * 128 + lane * 4];
        asm volatile("red.global.add.v4.f32 [%0], {%1,%2,%3,%4};"
                     :: "l"(p), "f"(v.x), "f"(v.y), "f"(v.z), "f"(v.w) : "memory");
    } else {
        float2 v = *(const float2*)&Hm[(size_t)s * 64 + lane * 2];
        v.x *= nrm; v.y *= nrm;
        float* p = &out[(size_t)d * 64 + lane * 2];
        asm volatile("red.global.add.v2.f32 [%0], {%1,%2};"
                     :: "l"(p), "f"(v.x), "f"(v.y) : "memory");
    }
}

__global__ void k_leaky(float* __restrict__ X, size_t n) {
    size_t i = (size_t)blockIdx.x * blockDim.x + threadIdx.x;
    if (i < n) { float v = X[i]; X[i] = v > 0.f ? v : SLOPE_ * v; }
}

// ---------------- depthwise 5x5 conv, channel-last, SAME pad, +bias, leaky ----------------
__global__ void k_dwconv(const float* __restrict__ In, const float* __restrict__ dw,
                         const float* __restrict__ db, float* __restrict__ Out) {
    __shared__ float wt[25 * 64];
    int tid = threadIdx.x;
    for (int i = tid; i < 25 * 64; i += 256) {
        int t = i >> 6, c = i & 63;
        wt[i] = dw[c * 25 + t];
    }
    __syncthreads();
    int c4 = tid & 15;
    int p = blockIdx.x * 16 + (tid >> 4);
    int y = p / Ww_, x = p % Ww_;
    float4 acc = {0.f, 0.f, 0.f, 0.f};
#pragma unroll
    for (int ky = 0; ky < 5; ++ky) {
        int yy = y + ky - 2;
        if (yy < 0 || yy >= Hh_) continue;
#pragma unroll
        for (int kx = 0; kx < 5; ++kx) {
            int xx = x + kx - 2;
            if (xx < 0 || xx >= Ww_) continue;
            float4 v  = *(const float4*)&In[((size_t)yy * Ww_ + xx) * 64 + c4 * 4];
            float4 wv = *(const float4*)&wt[(ky * 5 + kx) * 64 + c4 * 4];
            acc.x += v.x * wv.x; acc.y += v.y * wv.y;
            acc.z += v.z * wv.z; acc.w += v.w * wv.w;
        }
    }
    float4 b = *(const float4*)&db[c4 * 4];
    acc.x += b.x; acc.y += b.y; acc.z += b.z; acc.w += b.w;
    acc.x = acc.x > 0.f ? acc.x : SLOPE_ * acc.x;
    acc.y = acc.y > 0.f ? acc.y : SLOPE_ * acc.y;
    acc.z = acc.z > 0.f ? acc.z : SLOPE_ * acc.z;
    acc.w = acc.w > 0.f ? acc.w : SLOPE_ * acc.w;
    *(float4*)&Out[(size_t)p * 64 + c4 * 4] = acc;
}

// ---------------- head: concat -> linear(128,16) -> softmax ----------------
__global__ void k_final(const float* __restrict__ G, const float* __restrict__ Cn,
                        const float* __restrict__ lw, const float* __restrict__ lb,
                        float* __restrict__ out) {
    __shared__ float slw[128 * 16];
    __shared__ float slb[16];
    __shared__ float sg[16][64];
    __shared__ float sc[16][64];
    int tid = threadIdx.x;  // 256
    for (int i = tid; i < 2048; i += 256) slw[i] = lw[i];
    if (tid < 16) slb[tid] = lb[tid];
    int tx = tid & 15, ty = tid >> 4;
    size_t row = (size_t)blockIdx.x * 16 + ty;
    *(float4*)&sg[ty][tx * 4] = *(const float4*)&G[row * 64 + tx * 4];
    *(float4*)&sc[ty][tx * 4] = *(const float4*)&Cn[row * 64 + tx * 4];
    __syncthreads();
    float acc = slb[tx];
#pragma unroll 4
    for (int k = 0; k < 64; ++k) acc += sg[ty][k] * slw[k * 16 + tx];
#pragma unroll 4
    for (int k = 0; k < 64; ++k) acc += sc[ty][k] * slw[(64 + k) * 16 + tx];
    float mx = acc;
#pragma unroll
    for (int o = 8; o > 0; o >>= 1) mx = fmaxf(mx, __shfl_xor_sync(0xffffffffu, mx, o));
    float e = __expf(acc - mx);
    float sum = e;
#pragma unroll
    for (int o = 8; o > 0; o >>= 1) sum += __shfl_xor_sync(0xffffffffu, sum, o);
    out[row * 16 + tx] = e / sum;
}

// ---------------- host launchers ----------------
template <int K, int M, int BM, int TCOLS, bool LEAKY>
static void launch_gemm(const float* X, float* Y) {
    size_t smem = (size_t)(K * M + BM * (K + 1)) * 4;
    cudaFuncSetAttribute(k_gemm<K, M, BM, TCOLS, LEAKY>,
                         cudaFuncAttributeMaxDynamicSharedMemorySize, (int)smem);
    k_gemm<K, M, BM, TCOLS, LEAKY><<<N_ / BM, 256, smem>>>(X, Y);
}

template <int DOUT>
static void gnn_layer(const float* bng, const float* bnb, const float* w, const float* b,
                      const int* src, const int* dst, float* pP, float* pQ, float* pH) {
    k_rownorm<<<N_ * 32 / 256, 256>>>(pP, pQ);
    k_zero_stats<<<1, 256>>>();
    k_colstats<128><<<128, 128>>>(pQ);
    k_foldw<128, DOUT><<<(128 * DOUT) / 256, 256>>>(w, bng);
    k_foldb<128, DOUT><<<1, DOUT>>>(w, bng, bnb, nullptr);
    launch_gemm<128, DOUT, (DOUT == 128 ? 128 : 256), (DOUT == 128 ? 16 : 8), false>(pQ, pH);
    k_gcn_init<DOUT><<<(N_ * DOUT) / 256, 256>>>(pH, b, pP);
    k_gcn_scatter<DOUT><<<E_ * 32 / 256, 256>>>(pH, src, dst, pP);
    k_leaky<<<(N_ * DOUT) / 256, 256>>>(pP, (size_t)N_ * DOUT);
}

extern "C" void kernel_launch(void* const* d_in, const int* in_sizes, int n_in,
                              void* d_out, int out_size) {
    const float* x   = (const float*)d_in[0];
    const int*   ei  = (const int*)d_in[1];
    const int*   src = ei;
    const int*   dst = ei + E_;
    const float* dn_bn1_g = (const float*)d_in[2];
    const float* dn_bn1_b = (const float*)d_in[3];
    const float* dn_w1    = (const float*)d_in[4];
    const float* dn_b1    = (const float*)d_in[5];
    const float* dn_bn2_g = (const float*)d_in[6];
    const float* dn_bn2_b = (const float*)d_in[7];
    const float* dn_w2    = (const float*)d_in[8];
    const float* dn_b2    = (const float*)d_in[9];
    const float* cnn_bn_g = (const float*)d_in[10];
    const float* cnn_bn_b = (const float*)d_in[11];
    const float* cnn_pw   = (const float*)d_in[12];
    const float* cnn_dw   = (const float*)d_in[13];
    const float* cnn_db   = (const float*)d_in[14];
    const float* g1_bn_g  = (const float*)d_in[15];
    const float* g1_bn_b  = (const float*)d_in[16];
    const float* g1_w     = (const float*)d_in[17];
    const float* g1_b     = (const float*)d_in[18];
    const float* g2_bn_g  = (const float*)d_in[19];
    const float* g2_bn_b  = (const float*)d_in[20];
    const float* g2_w     = (const float*)d_in[21];
    const float* g2_b     = (const float*)d_in[22];
    const float* g3_bn_g  = (const float*)d_in[23];
    const float* g3_bn_b  = (const float*)d_in[24];
    const float* g3_w     = (const float*)d_in[25];
    const float* g3_b     = (const float*)d_in[26];
    const float* lin_w    = (const float*)d_in[27];
    const float* lin_b    = (const float*)d_in[28];
    float* out = (float*)d_out;

    float *pP, *pQ, *pH, *pC, *pCR;
    cudaGetSymbolAddress((void**)&pP, g_P);
    cudaGetSymbolAddress((void**)&pQ, g_Q);
    cudaGetSymbolAddress((void**)&pH, g_Hm);
    cudaGetSymbolAddress((void**)&pC, g_cnn);
    cudaGetSymbolAddress((void**)&pCR, g_cnnres);

    // degrees (independent of features)
    k_deg_init<<<(N_ + 255) / 256, 256>>>();
    k_deg_count<<<(E_ + 255) / 256, 256>>>(dst);
    k_deg_fin<<<(N_ + 255) / 256, 256>>>();

    // --- CNN_denoise ---
    k_zero_stats<<<1, 256>>>();
    k_colstats<200><<<128, 200>>>(x);
    k_foldw<200, 128><<<100, 256>>>(dn_w1, dn_bn1_g);
    k_foldb<200, 128><<<1, 128>>>(dn_w1, dn_bn1_g, dn_bn1_b, dn_b1);
    launch_gemm<200, 128, 128, 16, true>(x, pQ);

    k_zero_stats<<<1, 256>>>();
    k_colstats<128><<<128, 128>>>(pQ);
    k_foldw<128, 128><<<64, 256>>>(dn_w2, dn_bn2_g);
    k_foldb<128, 128><<<1, 128>>>(dn_w2, dn_bn2_g, dn_bn2_b, dn_b2);
    launch_gemm<128, 128, 128, 16, true>(pQ, pP);   // pP = clean

    // --- CNN branch ---
    k_zero_stats<<<1, 256>>>();
    k_colstats<128><<<128, 128>>>(pP);
    k_foldw<128, 64><<<32, 256>>>(cnn_pw, cnn_bn_g);
    k_foldb<128, 64><<<1, 64>>>(cnn_pw, cnn_bn_g, cnn_bn_b, nullptr);
    launch_gemm<128, 64, 256, 8, true>(pP, pC);
    k_dwconv<<<N_ / 16, 256>>>(pC, cnn_dw, cnn_db, pCR);

    // --- GCN branch (3 layers) ---
    gnn_layer<128>(g1_bn_g, g1_bn_b, g1_w, g1_b, src, dst, pP, pQ, pH);
    gnn_layer<128>(g2_bn_g, g2_bn_b, g2_w, g2_b, src, dst, pP, pQ, pH);
    gnn_layer<64>(g3_bn_g, g3_bn_b, g3_w, g3_b, src, dst, pP, pQ, pH);

    // --- head ---
    k_final<<<N_ / 16, 256>>>(pP, pCR, lin_w, lin_b, out);
}

// round 2
// speedup vs baseline: 1.3582x; 1.3582x over previous
#include <cuda_runtime.h>
#include <cstdint>
#include <cstddef>

// ---------------- problem constants ----------------
#define Hh_ 384
#define Ww_ 384
#define C_ 200
#define N_ 147456           // Hh_*Ww_
#define E_ 1179648
#define HIDE_ 128
#define OUT_ 64
#define NCLS_ 16
#define EPS_ 1e-5f
#define SLOPE_ 0.01f
#define NBLK_ 576           // N_/256

// ---------------- scratch (device globals; no allocation allowed) ----------------
__device__ float g_P[(size_t)N_ * 128];     // layer in/out (clean, gcn out)
__device__ float g_Q[(size_t)N_ * 128];     // normalized / staging
__device__ float g_Hm[(size_t)N_ * 128];    // h_scaled = dinv[i] * (x @ W + bf)
__device__ float g_cnn[(size_t)N_ * 64];
__device__ float g_cnnres[(size_t)N_ * 64];
__device__ float g_dinv[N_];
__device__ float g_sum[256];
__device__ float g_sq[256];
__device__ float g_wf[C_ * 128];            // folded weights (max 200x128)
__device__ float g_bf[128];                 // folded bias
// CSR
__device__ int g_degi[N_];
__device__ int g_rowptr[N_ + 1];
__device__ int g_cursor[N_];
__device__ int g_blksum[NBLK_];
__device__ int g_col[E_];

// ---------------- small utility kernels ----------------
__global__ void k_zero_stats() {
    int i = threadIdx.x;
    if (i < 256) { g_sum[i] = 0.f; g_sq[i] = 0.f; }
}

// plain column stats (for non-normalized inputs): blockDim == C
template <int C>
__global__ void k_colstats(const float* __restrict__ X) {
    const int c = threadIdx.x;
    const int rpb = N_ / 128;
    const int r0 = blockIdx.x * rpb;
    float s = 0.f, q = 0.f;
    for (int r = r0; r < r0 + rpb; ++r) {
        float v = X[(size_t)r * C + c];
        s += v; q += v * v;
    }
    atomicAdd(&g_sum[c], s);
    atomicAdd(&g_sq[c], q);
}

// fused rownorm (F.normalize) + column stats of the normalized output.
// Optionally applies leaky-relu to the input on load (fuses the post-GCN activation).
// grid 288 x 256; warp per row, 64 rows per warp.
template <bool LK>
__global__ void k_rownorm_stats(const float* __restrict__ X, float* __restrict__ Y) {
    __shared__ float sp[8][128];
    __shared__ float sq[8][128];
    const int tid = threadIdx.x;
    const int wid = tid >> 5, lane = tid & 31;
    const int gw = blockIdx.x * 8 + wid;
    float4 s4 = {0.f, 0.f, 0.f, 0.f}, q4 = {0.f, 0.f, 0.f, 0.f};
    for (int r = gw; r < N_; r += 288 * 8) {
        float4 v = *(const float4*)&X[(size_t)r * 128 + lane * 4];
        if (LK) {
            v.x = v.x > 0.f ? v.x : SLOPE_ * v.x;
            v.y = v.y > 0.f ? v.y : SLOPE_ * v.y;
            v.z = v.z > 0.f ? v.z : SLOPE_ * v.z;
            v.w = v.w > 0.f ? v.w : SLOPE_ * v.w;
        }
        float ss = v.x * v.x + v.y * v.y + v.z * v.z + v.w * v.w;
#pragma unroll
        for (int o = 16; o > 0; o >>= 1) ss += __shfl_xor_sync(0xffffffffu, ss, o);
        float inv = 1.0f / fmaxf(sqrtf(ss), 1e-12f);
        v.x *= inv; v.y *= inv; v.z *= inv; v.w *= inv;
        *(float4*)&Y[(size_t)r * 128 + lane * 4] = v;
        s4.x += v.x; s4.y += v.y; s4.z += v.z; s4.w += v.w;
        q4.x += v.x * v.x; q4.y += v.y * v.y; q4.z += v.z * v.z; q4.w += v.w * v.w;
    }
    sp[wid][lane * 4 + 0] = s4.x; sp[wid][lane * 4 + 1] = s4.y;
    sp[wid][lane * 4 + 2] = s4.z; sp[wid][lane * 4 + 3] = s4.w;
    sq[wid][lane * 4 + 0] = q4.x; sq[wid][lane * 4 + 1] = q4.y;
    sq[wid][lane * 4 + 2] = q4.z; sq[wid][lane * 4 + 3] = q4.w;
    __syncthreads();
    if (tid < 128) {
        float a = 0.f, b = 0.f;
#pragma unroll
        for (int w = 0; w < 8; ++w) { a += sp[w][tid]; b += sq[w][tid]; }
        atomicAdd(&g_sum[tid], a);
        atomicAdd(&g_sq[tid], b);
    }
}

// merged fold: blocks [0, K*M/256) fold weights, last block folds bias
template <int K, int M>
__global__ void k_fold(const float* __restrict__ W, const float* __restrict__ bng,
                       const float* __restrict__ bnb, const float* __restrict__ bias) {
    if (blockIdx.x == (K * M) / 256) {
        int m = threadIdx.x;
        if (m < M) {
            float acc = bias ? bias[m] : 0.0f;
            for (int c = 0; c < K; ++c) {
                float mean = g_sum[c] * (1.0f / N_);
                float var  = g_sq[c] * (1.0f / N_) - mean * mean;
                float scale = bng[c] * rsqrtf(var + EPS_);
                float shift = bnb[c] - mean * scale;
                acc += shift * W[c * M + m];
            }
            g_bf[m] = acc;
        }
        return;
    }
    int i = blockIdx.x * 256 + threadIdx.x;
    int c = i / M;
    float mean = g_sum[c] * (1.0f / N_);
    float var  = g_sq[c] * (1.0f / N_) - mean * mean;
    float scale = bng[c] * rsqrtf(var + EPS_);
    g_wf[i] = scale * W[i];
}

// ---------------- GEMM: Y[N,M] = epi(X[N,K] @ g_wf + g_bf) ----------------
// EPI 0: leaky.  EPI 1: scale row by dinv[row] (for GCN h-scaling), no leaky.
template <int K, int M, int BM, int TCOLS, int EPI>
__global__ __launch_bounds__(256, 1)
void k_gemm(const float* __restrict__ X, float* __restrict__ Y) {
    extern __shared__ float sm[];
    float* Ws = sm;                 // K*M
    float* Xs = sm + K * M;         // BM*(K+4)
    const int tid = threadIdx.x;
    const size_t row0 = (size_t)blockIdx.x * BM;

    for (int i = tid; i < K * M; i += 256) Ws[i] = g_wf[i];
    for (int q = tid; q < BM * (K / 4); q += 256) {
        int r = q / (K / 4), kq = q - r * (K / 4);
        *(float4*)&Xs[r * (K + 4) + kq * 4] =
            *(const float4*)&X[(row0 + r) * K + kq * 4];
    }
    __syncthreads();

    const int tc = tid % TCOLS, tr = tid / TCOLS;
    const int c0 = tc * 8, r0 = tr * 8;

    unsigned long long acc[8][4];
    unsigned long long binit[4];
#pragma unroll
    for (int j = 0; j < 4; ++j) {
        unsigned lo = __float_as_uint(g_bf[c0 + 2 * j]);
        unsigned hi = __float_as_uint(g_bf[c0 + 2 * j + 1]);
        asm("mov.b64 %0, {%1,%2};" : "=l"(binit[j]) : "r"(lo), "r"(hi));
    }
#pragma unroll
    for (int i = 0; i < 8; ++i)
#pragma unroll
        for (int j = 0; j < 4; ++j) acc[i][j] = binit[j];

    for (int kk = 0; kk < K; kk += 4) {
        float xv[8][4];
#pragma unroll
        for (int i = 0; i < 8; ++i) {
            float4 t = *(const float4*)&Xs[(r0 + i) * (K + 4) + kk];
            xv[i][0] = t.x; xv[i][1] = t.y; xv[i][2] = t.z; xv[i][3] = t.w;
        }
#pragma unroll
        for (int q = 0; q < 4; ++q) {
            const int k = kk + q;
            const ulonglong2 wA = *(const ulonglong2*)&Ws[k * M + c0];
            const ulonglong2 wB = *(const ulonglong2*)&Ws[k * M + c0 + 4];
#pragma unroll
            for (int i = 0; i < 8; ++i) {
                unsigned xu = __float_as_uint(xv[i][q]);
                unsigned long long xp;
                asm("mov.b64 %0, {%1,%1};" : "=l"(xp) : "r"(xu));
                asm("fma.rn.f32x2 %0, %1, %2, %0;" : "+l"(acc[i][0]) : "l"(xp), "l"(wA.x));
                asm("fma.rn.f32x2 %0, %1, %2, %0;" : "+l"(acc[i][1]) : "l"(xp), "l"(wA.y));
                asm("fma.rn.f32x2 %0, %1, %2, %0;" : "+l"(acc[i][2]) : "l"(xp), "l"(wB.x));
                asm("fma.rn.f32x2 %0, %1, %2, %0;" : "+l"(acc[i][3]) : "l"(xp), "l"(wB.y));
            }
        }
    }

#pragma unroll
    for (int i = 0; i < 8; ++i) {
        float outv[8];
#pragma unroll
        for (int j = 0; j < 4; ++j) {
            unsigned lo, hi;
            asm("mov.b64 {%0,%1}, %2;" : "=r"(lo), "=r"(hi) : "l"(acc[i][j]));
            outv[2 * j]     = __uint_as_float(lo);
            outv[2 * j + 1] = __uint_as_float(hi);
        }
        if (EPI == 0) {
#pragma unroll
            for (int j = 0; j < 8; ++j) outv[j] = outv[j] > 0.f ? outv[j] : SLOPE_ * outv[j];
        } else {
            float dv = g_dinv[row0 + r0 + i];
#pragma unroll
            for (int j = 0; j < 8; ++j) outv[j] *= dv;
        }
        float* yp = &Y[(row0 + r0 + i) * M + c0];
        *(float4*)(yp)     = *(float4*)&outv[0];
        *(float4*)(yp + 4) = *(float4*)&outv[4];
    }
}

// ---------------- CSR build ----------------
__global__ void k_deg_zero() {
    int i = blockIdx.x * blockDim.x + threadIdx.x;
    if (i < N_) g_degi[i] = 0;
}
__global__ void k_deg_count(const int* __restrict__ dst) {
    int e = blockIdx.x * blockDim.x + threadIdx.x;
    if (e < E_) atomicAdd(&g_degi[dst[e]], 1);
}
__global__ void k_scan1() {   // 576 blocks x 256: exclusive scan within block
    __shared__ int s[256];
    int t = threadIdx.x;
    int idx = blockIdx.x * 256 + t;
    int v = g_degi[idx];
    s[t] = v;
    __syncthreads();
#pragma unroll
    for (int off = 1; off < 256; off <<= 1) {
        int a = 0;
        if (t >= off) a = s[t - off];
        __syncthreads();
        s[t] += a;
        __syncthreads();
    }
    g_rowptr[idx] = s[t] - v;
    if (t == 255) g_blksum[blockIdx.x] = s[255];
}
__global__ void k_scan2() {   // 1 block x 1024: inclusive scan of 576 block sums
    __shared__ int s[NBLK_];
    int t = threadIdx.x;
    if (t < NBLK_) s[t] = g_blksum[t];
    __syncthreads();
    for (int off = 1; off < NBLK_; off <<= 1) {
        int a = 0;
        if (t >= off && t < NBLK_) a = s[t - off];
        __syncthreads();
        if (t < NBLK_) s[t] += a;
        __syncthreads();
    }
    if (t < NBLK_) g_blksum[t] = s[t];
}
__global__ void k_scan3() {   // finalize rowptr, cursor, dinv
    int idx = blockIdx.x * 256 + threadIdx.x;
    int off = blockIdx.x == 0 ? 0 : g_blksum[blockIdx.x - 1];
    int rp = g_rowptr[idx] + off;
    g_rowptr[idx] = rp;
    g_cursor[idx] = rp;
    g_dinv[idx] = rsqrtf((float)g_degi[idx] + 1.0f);
    if (idx == 0) g_rowptr[N_] = E_;
}
__global__ void k_csr_fill(const int* __restrict__ src, const int* __restrict__ dst) {
    int e = blockIdx.x * blockDim.x + threadIdx.x;
    if (e < E_) {
        int pos = atomicAdd(&g_cursor[dst[e]], 1);
        g_col[pos] = src[e];
    }
}

// ---------------- GCN gather: out[i] = gb + dinv[i] * (Hs[i] + sum_nbr Hs[s]) ----------------
// Hs is pre-scaled by dinv of its own row. warp per node.
__global__ void k_gather128(const float* __restrict__ Hs, const float* __restrict__ gb,
                            float* __restrict__ out) {
    int i = (int)(((size_t)blockIdx.x * blockDim.x + threadIdx.x) >> 5);
    if (i >= N_) return;
    int lane = threadIdx.x & 31;
    int beg = g_rowptr[i], end = g_rowptr[i + 1];
    float4 acc = *(const float4*)&Hs[(size_t)i * 128 + lane * 4];
    for (int base = beg; base < end; base += 32) {
        int e = base + lane;
        int sidx = (e < end) ? g_col[e] : 0;
        int cnt = min(32, end - base);
        int j = 0;
        for (; j + 4 <= cnt; j += 4) {
            int s0 = __shfl_sync(0xffffffffu, sidx, j);
            int s1 = __shfl_sync(0xffffffffu, sidx, j + 1);
            int s2 = __shfl_sync(0xffffffffu, sidx, j + 2);
            int s3 = __shfl_sync(0xffffffffu, sidx, j + 3);
            float4 v0 = *(const float4*)&Hs[(size_t)s0 * 128 + lane * 4];
            float4 v1 = *(const float4*)&Hs[(size_t)s1 * 128 + lane * 4];
            float4 v2 = *(const float4*)&Hs[(size_t)s2 * 128 + lane * 4];
            float4 v3 = *(const float4*)&Hs[(size_t)s3 * 128 + lane * 4];
            acc.x += v0.x + v1.x + v2.x + v3.x;
            acc.y += v0.y + v1.y + v2.y + v3.y;
            acc.z += v0.z + v1.z + v2.z + v3.z;
            acc.w += v0.w + v1.w + v2.w + v3.w;
        }
        for (; j < cnt; ++j) {
            int s = __shfl_sync(0xffffffffu, sidx, j);
            float4 v = *(const float4*)&Hs[(size_t)s * 128 + lane * 4];
            acc.x += v.x; acc.y += v.y; acc.z += v.z; acc.w += v.w;
        }
    }
    float di = g_dinv[i];
    float4 b = *(const float4*)&gb[lane * 4];
    acc.x = b.x + di * acc.x;
    acc.y = b.y + di * acc.y;
    acc.z = b.z + di * acc.z;
    acc.w = b.w + di * acc.w;
    *(float4*)&out[(size_t)i * 128 + lane * 4] = acc;
}

__global__ void k_gather64(const float* __restrict__ Hs, const float* __restrict__ gb,
                           float* __restrict__ out) {
    int i = (int)(((size_t)blockIdx.x * blockDim.x + threadIdx.x) >> 5);
    if (i >= N_) return;
    int lane = threadIdx.x & 31;
    int beg = g_rowptr[i], end = g_rowptr[i + 1];
    float2 acc = *(const float2*)&Hs[(size_t)i * 64 + lane * 2];
    for (int base = beg; base < end; base += 32) {
        int e = base + lane;
        int sidx = (e < end) ? g_col[e] : 0;
        int cnt = min(32, end - base);
        int j = 0;
        for (; j + 4 <= cnt; j += 4) {
            int s0 = __shfl_sync(0xffffffffu, sidx, j);
            int s1 = __shfl_sync(0xffffffffu, sidx, j + 1);
            int s2 = __shfl_sync(0xffffffffu, sidx, j + 2);
            int s3 = __shfl_sync(0xffffffffu, sidx, j + 3);
            float2 v0 = *(const float2*)&Hs[(size_t)s0 * 64 + lane * 2];
            float2 v1 = *(const float2*)&Hs[(size_t)s1 * 64 + lane * 2];
            float2 v2 = *(const float2*)&Hs[(size_t)s2 * 64 + lane * 2];
            float2 v3 = *(const float2*)&Hs[(size_t)s3 * 64 + lane * 2];
            acc.x += v0.x + v1.x + v2.x + v3.x;
            acc.y += v0.y + v1.y + v2.y + v3.y;
        }
        for (; j < cnt; ++j) {
            int s = __shfl_sync(0xffffffffu, sidx, j);
            float2 v = *(const float2*)&Hs[(size_t)s * 64 + lane * 2];
            acc.x += v.x; acc.y += v.y;
        }
    }
    float di = g_dinv[i];
    float2 b = *(const float2*)&gb[lane * 2];
    acc.x = b.x + di * acc.x;
    acc.y = b.y + di * acc.y;
    *(float2*)&out[(size_t)i * 64 + lane * 2] = acc;
}

// ---------------- depthwise 5x5 conv, channel-last, SAME pad, +bias, leaky ----------------
__global__ void k_dwconv(const float* __restrict__ In, const float* __restrict__ dw,
                         const float* __restrict__ db, float* __restrict__ Out) {
    __shared__ float wt[25 * 64];
    int tid = threadIdx.x;
    for (int i = tid; i < 25 * 64; i += 256) {
        int t = i >> 6, c = i & 63;
        wt[i] = dw[c * 25 + t];
    }
    __syncthreads();
    int c4 = tid & 15;
    int p = blockIdx.x * 16 + (tid >> 4);
    int y = p / Ww_, x = p % Ww_;
    float4 acc = {0.f, 0.f, 0.f, 0.f};
#pragma unroll
    for (int ky = 0; ky < 5; ++ky) {
        int yy = y + ky - 2;
        if (yy < 0 || yy >= Hh_) continue;
#pragma unroll
        for (int kx = 0; kx < 5; ++kx) {
            int xx = x + kx - 2;
            if (xx < 0 || xx >= Ww_) continue;
            float4 v  = *(const float4*)&In[((size_t)yy * Ww_ + xx) * 64 + c4 * 4];
            float4 wv = *(const float4*)&wt[(ky * 5 + kx) * 64 + c4 * 4];
            acc.x += v.x * wv.x; acc.y += v.y * wv.y;
            acc.z += v.z * wv.z; acc.w += v.w * wv.w;
        }
    }
    float4 b = *(const float4*)&db[c4 * 4];
    acc.x += b.x; acc.y += b.y; acc.z += b.z; acc.w += b.w;
    acc.x = acc.x > 0.f ? acc.x : SLOPE_ * acc.x;
    acc.y = acc.y > 0.f ? acc.y : SLOPE_ * acc.y;
    acc.z = acc.z > 0.f ? acc.z : SLOPE_ * acc.z;
    acc.w = acc.w > 0.f ? acc.w : SLOPE_ * acc.w;
    *(float4*)&Out[(size_t)p * 64 + c4 * 4] = acc;
}

// ---------------- head: leaky(G) concat Cn -> linear(128,16) -> softmax ----------------
__global__ void k_final(const float* __restrict__ G, const float* __restrict__ Cn,
                        const float* __restrict__ lw, const float* __restrict__ lb,
                        float* __restrict__ out) {
    __shared__ float slw[128 * 16];
    __shared__ float slb[16];
    __shared__ float sg[16][64];
    __shared__ float sc[16][64];
    int tid = threadIdx.x;  // 256
    for (int i = tid; i < 2048; i += 256) slw[i] = lw[i];
    if (tid < 16) slb[tid] = lb[tid];
    int tx = tid & 15, ty = tid >> 4;
    size_t row = (size_t)blockIdx.x * 16 + ty;
    float4 gv = *(const float4*)&G[row * 64 + tx * 4];
    gv.x = gv.x > 0.f ? gv.x : SLOPE_ * gv.x;
    gv.y = gv.y > 0.f ? gv.y : SLOPE_ * gv.y;
    gv.z = gv.z > 0.f ? gv.z : SLOPE_ * gv.z;
    gv.w = gv.w > 0.f ? gv.w : SLOPE_ * gv.w;
    *(float4*)&sg[ty][tx * 4] = gv;
    *(float4*)&sc[ty][tx * 4] = *(const float4*)&Cn[row * 64 + tx * 4];
    __syncthreads();
    float acc = slb[tx];
#pragma unroll 4
    for (int k = 0; k < 64; ++k) acc += sg[ty][k] * slw[k * 16 + tx];
#pragma unroll 4
    for (int k = 0; k < 64; ++k) acc += sc[ty][k] * slw[(64 + k) * 16 + tx];
    float mx = acc;
#pragma unroll
    for (int o = 8; o > 0; o >>= 1) mx = fmaxf(mx, __shfl_xor_sync(0xffffffffu, mx, o));
    float e = __expf(acc - mx);
    float sum = e;
#pragma unroll
    for (int o = 8; o > 0; o >>= 1) sum += __shfl_xor_sync(0xffffffffu, sum, o);
    out[row * 16 + tx] = e / sum;
}

// ---------------- host launchers ----------------
template <int K, int M, int BM, int TCOLS, int EPI>
static void launch_gemm(const float* X, float* Y) {
    size_t smem = (size_t)(K * M + BM * (K + 4)) * 4;
    cudaFuncSetAttribute(k_gemm<K, M, BM, TCOLS, EPI>,
                         cudaFuncAttributeMaxDynamicSharedMemorySize, (int)smem);
    k_gemm<K, M, BM, TCOLS, EPI><<<N_ / BM, 256, smem>>>(X, Y);
}

template <int DOUT, bool LK_IN>
static void gnn_layer(const float* bng, const float* bnb, const float* w, const float* b,
                      float* pP, float* pQ, float* pH) {
    k_zero_stats<<<1, 256>>>();
    k_rownorm_stats<LK_IN><<<288, 256>>>(pP, pQ);
    k_fold<128, DOUT><<<(128 * DOUT) / 256 + 1, 256>>>(w, bng, bnb, nullptr);
    launch_gemm<128, DOUT, (DOUT == 128 ? 128 : 256), (DOUT == 128 ? 16 : 8), 1>(pQ, pH);
    if (DOUT == 128)
        k_gather128<<<(N_ * 32) / 256, 256>>>(pH, b, pP);
    else
        k_gather64<<<(N_ * 32) / 256, 256>>>(pH, b, pP);
}

extern "C" void kernel_launch(void* const* d_in, const int* in_sizes, int n_in,
                              void* d_out, int out_size) {
    const float* x   = (const float*)d_in[0];
    const int*   ei  = (const int*)d_in[1];
    const int*   src = ei;
    const int*   dst = ei + E_;
    const float* dn_bn1_g = (const float*)d_in[2];
    const float* dn_bn1_b = (const float*)d_in[3];
    const float* dn_w1    = (const float*)d_in[4];
    const float* dn_b1    = (const float*)d_in[5];
    const float* dn_bn2_g = (const float*)d_in[6];
    const float* dn_bn2_b = (const float*)d_in[7];
    const float* dn_w2    = (const float*)d_in[8];
    const float* dn_b2    = (const float*)d_in[9];
    const float* cnn_bn_g = (const float*)d_in[10];
    const float* cnn_bn_b = (const float*)d_in[11];
    const float* cnn_pw   = (const float*)d_in[12];
    const float* cnn_dw   = (const float*)d_in[13];
    const float* cnn_db   = (const float*)d_in[14];
    const float* g1_bn_g  = (const float*)d_in[15];
    const float* g1_bn_b  = (const float*)d_in[16];
    const float* g1_w     = (const float*)d_in[17];
    const float* g1_b     = (const float*)d_in[18];
    const float* g2_bn_g  = (const float*)d_in[19];
    const float* g2_bn_b  = (const float*)d_in[20];
    const float* g2_w     = (const float*)d_in[21];
    const float* g2_b     = (const float*)d_in[22];
    const float* g3_bn_g  = (const float*)d_in[23];
    const float* g3_bn_b  = (const float*)d_in[24];
    const float* g3_w     = (const float*)d_in[25];
    const float* g3_b     = (const float*)d_in[26];
    const float* lin_w    = (const float*)d_in[27];
    const float* lin_b    = (const float*)d_in[28];
    float* out = (float*)d_out;

    float *pP, *pQ, *pH, *pC, *pCR;
    cudaGetSymbolAddress((void**)&pP, g_P);
    cudaGetSymbolAddress((void**)&pQ, g_Q);
    cudaGetSymbolAddress((void**)&pH, g_Hm);
    cudaGetSymbolAddress((void**)&pC, g_cnn);
    cudaGetSymbolAddress((void**)&pCR, g_cnnres);

    // --- CSR build + dinv ---
    k_deg_zero<<<(N_ + 255) / 256, 256>>>();
    k_deg_count<<<(E_ + 255) / 256, 256>>>(dst);
    k_scan1<<<NBLK_, 256>>>();
    k_scan2<<<1, 1024>>>();
    k_scan3<<<NBLK_, 256>>>();
    k_csr_fill<<<(E_ + 255) / 256, 256>>>(src, dst);

    // --- CNN_denoise ---
    k_zero_stats<<<1, 256>>>();
    k_colstats<200><<<128, 200>>>(x);
    k_fold<200, 128><<<101, 256>>>(dn_w1, dn_bn1_g, dn_bn1_b, dn_b1);
    launch_gemm<200, 128, 128, 16, 0>(x, pQ);

    k_zero_stats<<<1, 256>>>();
    k_colstats<128><<<128, 128>>>(pQ);
    k_fold<128, 128><<<65, 256>>>(dn_w2, dn_bn2_g, dn_bn2_b, dn_b2);
    launch_gemm<128, 128, 128, 16, 0>(pQ, pP);   // pP = clean

    // --- CNN branch ---
    k_zero_stats<<<1, 256>>>();
    k_colstats<128><<<128, 128>>>(pP);
    k_fold<128, 64><<<33, 256>>>(cnn_pw, cnn_bn_g, cnn_bn_b, nullptr);
    launch_gemm<128, 64, 256, 8, 0>(pP, pC);
    k_dwconv<<<N_ / 16, 256>>>(pC, cnn_dw, cnn_db, pCR);

    // --- GCN branch (3 layers) ---
    gnn_layer<128, false>(g1_bn_g, g1_bn_b, g1_w, g1_b, pP, pQ, pH);
    gnn_layer<128, true >(g2_bn_g, g2_bn_b, g2_w, g2_b, pP, pQ, pH);
    gnn_layer<64,  true >(g3_bn_g, g3_bn_b, g3_w, g3_b, pP, pQ, pH);

    // --- head ---
    k_final<<<N_ / 16, 256>>>(pP, pCR, lin_w, lin_b, out);
}